// round 4
// baseline (speedup 1.0000x reference)
#include <cuda_runtime.h>
#include <math.h>

#define FF      20
#define ED      16
#define VOCAB   50000
#define VTOT    (FF * VOCAB)       /* 1,000,000 */
#define NT      512
#define EDP     17                 /* padded stride: odd -> conflict-free scalar reads */

__global__ __launch_bounds__(NT, 4)
void ffm_kernel(const int* __restrict__ x,
                const float* __restrict__ Wl,
                const float* __restrict__ Wc,
                const float* __restrict__ bias,
                float* __restrict__ out)
{
    __shared__ float S[FF][FF][EDP];     // S[f][g][e] = Wc[g, xo[f], e]
    __shared__ int   xo[FF];
    __shared__ float red[NT / 32];

    const int b = blockIdx.x;
    const int t = threadIdx.x;

    if (t < FF) xo[t] = x[b * FF + t] + t * VOCAB;
    __syncthreads();

    // ---- gather phase: 20*20 vectors of 16 floats = 1600 float4 tasks ----
    #pragma unroll
    for (int task = t; task < FF * FF * 4; task += NT) {
        const int c  = task & 3;
        const int fg = task >> 2;
        const int g  = fg % FF;
        const int f  = fg / FF;
        const float4 v = __ldg(reinterpret_cast<const float4*>(
                               Wc + ((size_t)g * VTOT + (size_t)xo[f]) * ED) + c);
        float* dst = &S[f][g][c * 4];
        dst[0] = v.x; dst[1] = v.y; dst[2] = v.z; dst[3] = v.w;
    }
    __syncthreads();

    // ---- compute phase: ordered pairs (i != j); sum = 2 * cross ----
    float partial = 0.0f;
    if (t < FF * FF) {
        const int i = t / FF;
        const int j = t % FF;
        if (i != j) {
            float s = 0.0f;
            #pragma unroll
            for (int e = 0; e < ED; e++)
                s = fmaf(S[i][j][e], S[j][i][e], s);
            partial = 0.5f * s;
        }
    }
    if (t < FF) partial += __ldg(Wl + xo[t]);   // linear term gather

    // ---- block reduction ----
    #pragma unroll
    for (int o = 16; o > 0; o >>= 1)
        partial += __shfl_down_sync(0xffffffffu, partial, o);
    if ((t & 31) == 0) red[t >> 5] = partial;
    __syncthreads();

    if (t == 0) {
        float z = bias[0];
        #pragma unroll
        for (int w = 0; w < NT / 32; w++) z += red[w];
        out[b] = 1.0f / (1.0f + expf(-z));
    }
}

extern "C" void kernel_launch(void* const* d_in, const int* in_sizes, int n_in,
                              void* d_out, int out_size)
{
    const int*   x    = (const int*)  d_in[0];   // (4096, 20) int32
    const float* Wl   = (const float*)d_in[1];   // (1e6, 1)  f32
    const float* Wc   = (const float*)d_in[2];   // (20, 1e6, 16) f32
    const float* bias = (const float*)d_in[3];   // (1,) f32
    float*       out  = (float*)d_out;           // (4096,) f32

    ffm_kernel<<<out_size, NT>>>(x, Wl, Wc, bias, out);
}